// round 14
// baseline (speedup 1.0000x reference)
#include <cuda_runtime.h>
#include <math.h>

typedef unsigned long long u64;

// Problem constants
#define B_  10
#define T_  2048
#define I_  128
#define H_  256
#define L_  6
#define G4  (4 * H_)

// Kernel config
#define NBLK     24        // blocks per layer (144 blocks co-resident)
#define THREADS  448
#define ROWS_MAX 44
#define JC_MAX   11
#define PSLOT    5         // 4 chunk slots + pad
#define VST      264       // v row stride (256 + 8 pad)
#define HCREW0   192       // h-crew first tid (warps 6-13)

// Scratch (device globals: allocation-free contract)
__device__ float g_hseq[(size_t)L_ * (T_ + 1) * B_ * H_];
__device__ int   g_prog[L_ * NBLK * 32];

__global__ void lstm_init_kernel(const float* __restrict__ h0) {
    int tid = blockIdx.x * blockDim.x + threadIdx.x;
    if (tid < L_ * B_ * H_) {
        int l = tid / (B_ * H_);
        int rem = tid - l * (B_ * H_);
        g_hseq[((size_t)l * (T_ + 1)) * B_ * H_ + rem] = h0[tid];
    }
    if (tid < L_ * NBLK * 32) g_prog[tid] = 0;
}

__device__ __forceinline__ float tanh_approx(float x) {
    float y;
    asm("tanh.approx.f32 %0, %1;" : "=f"(y) : "f"(x));
    return y;
}
__device__ __forceinline__ int ld_acq_gpu(const int* p) {
    int v;
    asm volatile("ld.acquire.gpu.global.b32 %0, [%1];" : "=r"(v) : "l"(p));
    return v;
}
__device__ __forceinline__ int ld_acq_cta(const int* p) {
    int v;
    asm volatile("ld.acquire.cta.b32 %0, [%1];" : "=r"(v) : "l"(p));
    return v;
}
__device__ __forceinline__ void st_rel_cta(int* p, int v) {
    asm volatile("st.release.cta.b32 [%0], %1;" :: "l"(p), "r"(v));
}

// 64-wide chunk GEMM: 2 passes of 5 batches, packed f32x2
__device__ __forceinline__ void gemm64(const u64* wlo, const u64* whi,
                                       const float* vp0, float* po) {
    #pragma unroll
    for (int pass = 0; pass < 2; pass++) {
        u64 acc[5];
        #pragma unroll
        for (int b = 0; b < 5; b++) acc[b] = 0ULL;
        const float* vp = vp0 + (size_t)(pass * 5) * VST;
        #pragma unroll
        for (int k4 = 0; k4 < 16; k4++) {
            const u64 w0 = wlo[k4];
            const u64 w1 = whi[k4];
            #pragma unroll
            for (int b = 0; b < 5; b++) {
                const ulonglong2 v = *(const ulonglong2*)(vp + b * VST + k4 * 4);
                asm("fma.rn.f32x2 %0, %1, %2, %0;" : "+l"(acc[b]) : "l"(w0), "l"(v.x));
                asm("fma.rn.f32x2 %0, %1, %2, %0;" : "+l"(acc[b]) : "l"(w1), "l"(v.y));
            }
        }
        #pragma unroll
        for (int b = 0; b < 5; b++) {
            float lo, hi;
            asm("mov.b64 {%0, %1}, %2;" : "=f"(lo), "=f"(hi) : "l"(acc[b]));
            po[(pass * 5 + b) * PSLOT] = lo + hi;
        }
    }
}

__global__ void __launch_bounds__(THREADS, 1)
lstm_pipeline_kernel(const float* __restrict__ x,
                     const float* __restrict__ c0,
                     const float* __restrict__ Wih0,
                     const float* __restrict__ Wih,
                     const float* __restrict__ Whh,
                     const float* __restrict__ bih,
                     const float* __restrict__ bhh,
                     float* __restrict__ out)
{
    extern __shared__ float sm[];
    float* vx     = sm;                              // 2 * B * VST (input-v ring)
    float* vrec   = vx + 2 * B_ * VST;               // 2 * B * VST (rec-v ring)
    float* psum_x = vrec + 2 * B_ * VST;             // 2 * 44*10*PSLOT (ring)
    float* psum_h = psum_x + 2 * ROWS_MAX * B_ * PSLOT;
    float* csm    = psum_h + ROWS_MAX * B_ * PSLOT;  // 110
    float* bsm    = csm + JC_MAX * B_;               // 44
    int*   sfl    = (int*)(bsm + ROWS_MAX);          // [0]=xfl, [1]=hfl

    const int l     = blockIdx.x / NBLK;
    const int p     = blockIdx.x % NBLK;
    const int jbase = (p * H_) / NBLK;
    const int jend  = ((p + 1) * H_) / NBLK;
    const int jc    = jend - jbase;          // 10 or 11
    const int rows  = 4 * jc;
    const int KIN   = (l == 0) ? I_ : H_;
    const int nx    = KIN / 64;              // 2 or 4
    const int tid   = threadIdx.x;
    const int wid   = tid >> 5;
    const int jcB   = jc * B_;

    // ---- task maps ----
    const int xrr = tid % ROWS_MAX;
    const int xkc = tid / ROWS_MAX;
    const bool x_on = (tid < HCREW0) && (xrr < rows) && (xkc < nx);
    const int idx1 = tid - HCREW0;
    const int hrr = (idx1 >= 0) ? (idx1 % ROWS_MAX) : 0;
    const int hkc = (idx1 >= 0) ? (idx1 / ROWS_MAX) : 0;
    const bool h_on = (idx1 >= 0) && (idx1 < 4 * ROWS_MAX) && (hrr < rows);

    // ---- weights in registers (packed f32x2) ----
    u64 wlo[16], whi[16];
    {
        const float* wp = 0;
        if (tid < HCREW0 && x_on) {
            const int gate = xrr / jc, jl = xrr - gate * jc;
            const int g = gate * H_ + jbase + jl;
            wp = (l == 0) ? (Wih0 + (size_t)g * I_ + xkc * 64)
                          : (Wih + ((size_t)(l - 1) * G4 + g) * H_ + xkc * 64);
        } else if (idx1 >= 0 && h_on) {
            const int gate = hrr / jc, jl = hrr - gate * jc;
            const int g = gate * H_ + jbase + jl;
            wp = Whh + ((size_t)l * G4 + g) * H_ + hkc * 64;
        }
        if (wp) {
            #pragma unroll
            for (int k4 = 0; k4 < 16; k4++) {
                const u64* q = (const u64*)(wp + k4 * 4);
                wlo[k4] = q[0];
                whi[k4] = q[1];
            }
        } else {
            #pragma unroll
            for (int i = 0; i < 16; i++) { wlo[i] = 0ULL; whi[i] = 0ULL; }
        }
    }

    // ---- init smem ----
    for (int r = tid; r < rows; r += THREADS) {
        int gate = r / jc, jl = r - gate * jc;
        int g = gate * H_ + jbase + jl;
        bsm[r] = bih[l * G4 + g] + bhh[l * G4 + g];
    }
    for (int e = tid; e < jcB; e += THREADS) {
        int jl = e / B_, b = e - jl * B_;
        csm[e] = c0[((size_t)l * B_ + b) * H_ + jbase + jl];
    }
    for (int e = tid; e < 2 * ROWS_MAX * B_ * PSLOT; e += THREADS) psum_x[e] = 0.f;
    for (int e = tid; e < ROWS_MAX * B_ * PSLOT; e += THREADS) psum_h[e] = 0.f;
    // vrec slot 0 <- h(0) (written by init kernel this launch)
    {
        const float4* hp0 = (const float4*)(g_hseq +
            ((size_t)(l * (T_ + 1))) * B_ * H_);
        for (int e = tid; e < B_ * (H_ / 4); e += THREADS) {
            int b = e >> 6, k4 = e & 63;
            *(float4*)(vrec + b * VST + k4 * 4) = hp0[e];
        }
    }
    if (tid == 0) { sfl[0] = 0; sfl[1] = 0; }
    __syncthreads();   // last full-block barrier; crews diverge below

    if (wid < 6) {
        // ================= x-crew (warps 0-5, 192 threads) =================
        for (int t = 0; t < T_; t++) {
            // X1: wait lower-layer flags >= t+1 (l>0), hfl >= t-1 (ring free)
            if (l > 0 && tid < NBLK) {
                const int* f = &g_prog[((l - 1) * NBLK + tid) * 32];
                while (ld_acq_gpu(f) < t + 1) { }
            }
            while (ld_acq_cta(&sfl[1]) < t - 1) { }
            asm volatile("bar.sync 2, 192;" ::: "memory");
            // X2: build input v(t) into ring slot t&1
            float* vxs = vx + (t & 1) * B_ * VST;
            if (l == 0) {
                const float4* xp = (const float4*)x;
                for (int e = tid; e < B_ * (I_ / 4); e += HCREW0) {
                    int b = e >> 5, k4 = e & 31;       // I_/4 = 32
                    *(float4*)(vxs + b * VST + k4 * 4) =
                        xp[((size_t)b * T_ + t) * (I_ / 4) + k4];
                }
            } else {
                const float4* ip = (const float4*)(g_hseq +
                    ((size_t)((l - 1) * (T_ + 1) + t + 1)) * B_ * H_);
                for (int e = tid; e < B_ * (H_ / 4); e += HCREW0) {
                    int b = e >> 6, k4 = e & 63;       // H_/4 = 64
                    *(float4*)(vxs + b * VST + k4 * 4) = ip[e];
                }
            }
            asm volatile("bar.sync 2, 192;" ::: "memory");
            // X3: input GEMM into psum_x ring slot t&1
            if (x_on) {
                gemm64(wlo, whi, vxs + xkc * 64,
                       psum_x + (t & 1) * ROWS_MAX * B_ * PSLOT
                              + (xrr * B_) * PSLOT + xkc);
            }
            asm volatile("bar.sync 2, 192;" ::: "memory");
            if (tid == 0) st_rel_cta(&sfl[0], t + 1);
        }
    } else {
        // ================= h-crew (warps 6-13, 256 threads) =================
        const int htid = tid - HCREW0;               // 0..255
        for (int t = 0; t < T_; t++) {
            // Phase A: recurrent GEMM on vrec[t&1] (warps 6-11)
            if (h_on) {
                gemm64(wlo, whi, vrec + (t & 1) * B_ * VST + hkc * 64,
                       psum_h + (hrr * B_) * PSLOT + hkc);
            }
            asm volatile("bar.sync 1, 256;" ::: "memory");
            // Phase B: cell (warps 6-9) || poll + prefetch h(t+1) (warps 10-13)
            if (htid < 128) {
                if (htid < jcB) {
                    while (ld_acq_cta(&sfl[0]) < t + 1) { }
                    const int jl = htid / B_;
                    const int b  = htid - jl * B_;
                    const float* px = psum_x + (t & 1) * ROWS_MAX * B_ * PSLOT;
                    float gs[4];
                    #pragma unroll
                    for (int gate = 0; gate < 4; gate++) {
                        const int r = gate * jc + jl;
                        const float* ph = psum_h + (r * B_ + b) * PSLOT;
                        const float* pxx = px + (r * B_ + b) * PSLOT;
                        float sh = (ph[0] + ph[1]) + (ph[2] + ph[3]);
                        float sx = (pxx[0] + pxx[1]) + (pxx[2] + pxx[3]);
                        gs[gate] = bsm[r] + sh + sx;
                    }
                    float ig = fmaf(0.5f, tanh_approx(0.5f * gs[0]), 0.5f);
                    float fg = fmaf(0.5f, tanh_approx(0.5f * gs[1]), 0.5f);
                    float gg = tanh_approx(gs[2]);
                    float og = fmaf(0.5f, tanh_approx(0.5f * gs[3]), 0.5f);
                    float c  = fmaf(fg, csm[htid], ig * gg);
                    csm[htid] = c;
                    float* hout = g_hseq +
                        ((size_t)(l * (T_ + 1) + t + 1)) * B_ * H_;
                    hout[(size_t)b * H_ + jbase + jl] = og * tanh_approx(c);
                }
                asm volatile("bar.sync 4, 128;" ::: "memory");
                if (htid == 0) st_rel_cta(&sfl[1], t + 1);
                if (htid == 1) {
                    asm volatile("st.release.gpu.global.b32 [%0], %1;"
                                 :: "l"(&g_prog[(l * NBLK + p) * 32]),
                                    "r"(t + 1));
                }
            } else {
                // warps 10-13: warp 12 polls all own-layer flags >= t+1
                // (every block publishes t+1 concurrently in ITS phase B,
                //  never behind a barrier this poll gates -> no cycle)
                if (wid == 12 && (tid & 31) < NBLK) {
                    const int* f = &g_prog[(l * NBLK + (tid & 31)) * 32];
                    while (ld_acq_gpu(f) < t + 1) { }
                }
                asm volatile("bar.sync 6, 128;" ::: "memory");
                // prefetch h(t+1) -> vrec[(t+1)&1]  (128 threads, 5 f4 each)
                const float4* hp = (const float4*)(g_hseq +
                    ((size_t)(l * (T_ + 1) + t + 1)) * B_ * H_);
                float* vdst = vrec + ((t + 1) & 1) * B_ * VST;
                const int pt = htid - 128;           // 0..127
                #pragma unroll
                for (int i = 0; i < 5; i++) {
                    int e = pt + i * 128;
                    int b = e >> 6, k4 = e & 63;
                    *(float4*)(vdst + b * VST + k4 * 4) = hp[e];
                }
            }
            asm volatile("bar.sync 1, 256;" ::: "memory");
        }
        // final cell states
        if (htid < jcB) {
            int jl = htid / B_, b = htid - jl * B_;
            out[((size_t)l * B_ + b) * H_ + jbase + jl] = csm[htid];
        }
    }
}

#define SMEM_FLOATS (4 * B_ * VST + 3 * ROWS_MAX * B_ * PSLOT \
                     + JC_MAX * B_ + ROWS_MAX + 8)
#define SMEM_BYTES  (SMEM_FLOATS * (int)sizeof(float))

extern "C" void kernel_launch(void* const* d_in, const int* in_sizes, int n_in,
                              void* d_out, int out_size) {
    const float* x    = (const float*)d_in[0];
    const float* h0   = (const float*)d_in[1];
    const float* c0   = (const float*)d_in[2];
    const float* Wih0 = (const float*)d_in[3];
    const float* Wih  = (const float*)d_in[4];
    const float* Whh  = (const float*)d_in[5];
    const float* bih  = (const float*)d_in[6];
    const float* bhh  = (const float*)d_in[7];
    float* out = (float*)d_out;

    cudaFuncSetAttribute(lstm_pipeline_kernel,
                         cudaFuncAttributeMaxDynamicSharedMemorySize, SMEM_BYTES);

    lstm_init_kernel<<<64, 256>>>(h0);
    lstm_pipeline_kernel<<<L_ * NBLK, THREADS, SMEM_BYTES>>>(
        x, c0, Wih0, Wih, Whh, bih, bhh, out);
}

// round 15
// speedup vs baseline: 1.1251x; 1.1251x over previous
#include <cuda_runtime.h>
#include <math.h>

typedef unsigned long long u64;

// Problem constants
#define B_  10
#define T_  2048
#define I_  128
#define H_  256
#define L_  6
#define G4  (4 * H_)

// Kernel config
#define NBLK     24        // blocks per layer (144 blocks co-resident)
#define THREADS  448
#define ROWS_MAX 44
#define JC_MAX   11
#define PSLOT    5         // 4 chunk slots + pad
#define VST      264       // v row stride (256 + 8 pad)
#define HCREW0   192       // h-crew first tid (warps 6-13)
#define XDEPTH   4         // input-pipeline ring depth

// Scratch (device globals: allocation-free contract)
__device__ float g_hseq[(size_t)L_ * (T_ + 1) * B_ * H_];
__device__ int   g_prog[L_ * NBLK * 32];

__global__ void lstm_init_kernel(const float* __restrict__ h0) {
    int tid = blockIdx.x * blockDim.x + threadIdx.x;
    if (tid < L_ * B_ * H_) {
        int l = tid / (B_ * H_);
        int rem = tid - l * (B_ * H_);
        g_hseq[((size_t)l * (T_ + 1)) * B_ * H_ + rem] = h0[tid];
    }
    if (tid < L_ * NBLK * 32) g_prog[tid] = 0;
}

__device__ __forceinline__ float tanh_approx(float x) {
    float y;
    asm("tanh.approx.f32 %0, %1;" : "=f"(y) : "f"(x));
    return y;
}
__device__ __forceinline__ int ld_acq_gpu(const int* p) {
    int v;
    asm volatile("ld.acquire.gpu.global.b32 %0, [%1];" : "=r"(v) : "l"(p));
    return v;
}
__device__ __forceinline__ int ld_acq_cta(const int* p) {
    int v;
    asm volatile("ld.acquire.cta.b32 %0, [%1];" : "=r"(v) : "l"(p));
    return v;
}
__device__ __forceinline__ void st_rel_cta(int* p, int v) {
    asm volatile("st.release.cta.b32 [%0], %1;" :: "l"(p), "r"(v));
}

// 64-wide chunk GEMM: 2 passes of 5 batches, packed f32x2
__device__ __forceinline__ void gemm64(const u64* wlo, const u64* whi,
                                       const float* vp0, float* po) {
    #pragma unroll
    for (int pass = 0; pass < 2; pass++) {
        u64 acc[5];
        #pragma unroll
        for (int b = 0; b < 5; b++) acc[b] = 0ULL;
        const float* vp = vp0 + (size_t)(pass * 5) * VST;
        #pragma unroll
        for (int k4 = 0; k4 < 16; k4++) {
            const u64 w0 = wlo[k4];
            const u64 w1 = whi[k4];
            #pragma unroll
            for (int b = 0; b < 5; b++) {
                const ulonglong2 v = *(const ulonglong2*)(vp + b * VST + k4 * 4);
                asm("fma.rn.f32x2 %0, %1, %2, %0;" : "+l"(acc[b]) : "l"(w0), "l"(v.x));
                asm("fma.rn.f32x2 %0, %1, %2, %0;" : "+l"(acc[b]) : "l"(w1), "l"(v.y));
            }
        }
        #pragma unroll
        for (int b = 0; b < 5; b++) {
            float lo, hi;
            asm("mov.b64 {%0, %1}, %2;" : "=f"(lo), "=f"(hi) : "l"(acc[b]));
            po[(pass * 5 + b) * PSLOT] = lo + hi;
        }
    }
}

__global__ void __launch_bounds__(THREADS, 1)
lstm_pipeline_kernel(const float* __restrict__ x,
                     const float* __restrict__ c0,
                     const float* __restrict__ Wih0,
                     const float* __restrict__ Wih,
                     const float* __restrict__ Whh,
                     const float* __restrict__ bih,
                     const float* __restrict__ bhh,
                     float* __restrict__ out)
{
    extern __shared__ float sm[];
    float* vx     = sm;                               // XDEPTH * B * VST
    float* vrec   = vx + XDEPTH * B_ * VST;           // B * VST
    float* psum_x = vrec + B_ * VST;                  // XDEPTH * 44*10*PSLOT
    float* psum_h = psum_x + XDEPTH * ROWS_MAX * B_ * PSLOT;
    float* csm    = psum_h + ROWS_MAX * B_ * PSLOT;   // 110
    float* bsm    = csm + JC_MAX * B_;                // 44
    int*   sfl    = (int*)(bsm + ROWS_MAX);           // [0]=xfl, [1]=hfl

    const int l     = blockIdx.x / NBLK;
    const int p     = blockIdx.x % NBLK;
    const int jbase = (p * H_) / NBLK;
    const int jend  = ((p + 1) * H_) / NBLK;
    const int jc    = jend - jbase;          // 10 or 11
    const int rows  = 4 * jc;
    const int KIN   = (l == 0) ? I_ : H_;
    const int nx    = KIN / 64;              // 2 or 4
    const int tid   = threadIdx.x;
    const int wid   = tid >> 5;
    const int jcB   = jc * B_;

    // ---- task maps ----
    const int xrr = tid % ROWS_MAX;
    const int xkc = tid / ROWS_MAX;
    const bool x_on = (tid < HCREW0) && (xrr < rows) && (xkc < nx);
    const int idx1 = tid - HCREW0;
    const int hrr = (idx1 >= 0) ? (idx1 % ROWS_MAX) : 0;
    const int hkc = (idx1 >= 0) ? (idx1 / ROWS_MAX) : 0;
    const bool h_on = (idx1 >= 0) && (idx1 < 4 * ROWS_MAX) && (hrr < rows);

    // ---- weights in registers (packed f32x2) ----
    u64 wlo[16], whi[16];
    {
        const float* wp = 0;
        if (tid < HCREW0 && x_on) {
            const int gate = xrr / jc, jl = xrr - gate * jc;
            const int g = gate * H_ + jbase + jl;
            wp = (l == 0) ? (Wih0 + (size_t)g * I_ + xkc * 64)
                          : (Wih + ((size_t)(l - 1) * G4 + g) * H_ + xkc * 64);
        } else if (idx1 >= 0 && h_on) {
            const int gate = hrr / jc, jl = hrr - gate * jc;
            const int g = gate * H_ + jbase + jl;
            wp = Whh + ((size_t)l * G4 + g) * H_ + hkc * 64;
        }
        if (wp) {
            #pragma unroll
            for (int k4 = 0; k4 < 16; k4++) {
                const u64* q = (const u64*)(wp + k4 * 4);
                wlo[k4] = q[0];
                whi[k4] = q[1];
            }
        } else {
            #pragma unroll
            for (int i = 0; i < 16; i++) { wlo[i] = 0ULL; whi[i] = 0ULL; }
        }
    }

    // ---- init smem ----
    for (int r = tid; r < rows; r += THREADS) {
        int gate = r / jc, jl = r - gate * jc;
        int g = gate * H_ + jbase + jl;
        bsm[r] = bih[l * G4 + g] + bhh[l * G4 + g];
    }
    for (int e = tid; e < jcB; e += THREADS) {
        int jl = e / B_, b = e - jl * B_;
        csm[e] = c0[((size_t)l * B_ + b) * H_ + jbase + jl];
    }
    for (int e = tid; e < XDEPTH * ROWS_MAX * B_ * PSLOT; e += THREADS)
        psum_x[e] = 0.f;
    for (int e = tid; e < ROWS_MAX * B_ * PSLOT; e += THREADS) psum_h[e] = 0.f;
    if (tid == 0) { sfl[0] = 0; sfl[1] = 0; }
    __syncthreads();   // last full-block barrier; crews diverge below

    if (wid < 6) {
        // ================= x-crew (warps 0-5, 192 threads) =================
        // Runs up to XDEPTH steps ahead of the h-crew.
        for (int t = 0; t < T_; t++) {
            // X1: wait lower-layer flags >= t+1 (l>0); ring slot free:
            //     cell(t-XDEPTH) done  <=>  hfl >= t - (XDEPTH-1)
            if (l > 0 && tid < NBLK) {
                const int* f = &g_prog[((l - 1) * NBLK + tid) * 32];
                while (ld_acq_gpu(f) < t + 1) { }
            }
            while (ld_acq_cta(&sfl[1]) < t - (XDEPTH - 1)) { }
            asm volatile("bar.sync 2, 192;" ::: "memory");
            // X2: build input v(t) into ring slot t%XDEPTH
            float* vxs = vx + (t & (XDEPTH - 1)) * B_ * VST;
            if (l == 0) {
                const float4* xp = (const float4*)x;
                for (int e = tid; e < B_ * (I_ / 4); e += HCREW0) {
                    int b = e >> 5, k4 = e & 31;       // I_/4 = 32
                    *(float4*)(vxs + b * VST + k4 * 4) =
                        xp[((size_t)b * T_ + t) * (I_ / 4) + k4];
                }
            } else {
                const float4* ip = (const float4*)(g_hseq +
                    ((size_t)((l - 1) * (T_ + 1) + t + 1)) * B_ * H_);
                for (int e = tid; e < B_ * (H_ / 4); e += HCREW0) {
                    int b = e >> 6, k4 = e & 63;       // H_/4 = 64
                    *(float4*)(vxs + b * VST + k4 * 4) = ip[e];
                }
            }
            asm volatile("bar.sync 2, 192;" ::: "memory");
            // X3: input GEMM into psum_x ring slot t%XDEPTH
            if (x_on) {
                gemm64(wlo, whi, vxs + xkc * 64,
                       psum_x + (t & (XDEPTH - 1)) * ROWS_MAX * B_ * PSLOT
                              + (xrr * B_) * PSLOT + xkc);
            }
            asm volatile("bar.sync 2, 192;" ::: "memory");
            if (tid == 0) st_rel_cta(&sfl[0], t + 1);
        }
    } else {
        // ================= h-crew (warps 6-13, 256 threads) =================
        const int htid = tid - HCREW0;               // 0..255
        for (int t = 0; t < T_; t++) {
            // H1: build rec-v(t) from hseq[l][t]
            {
                const float4* hp = (const float4*)(g_hseq +
                    ((size_t)(l * (T_ + 1) + t)) * B_ * H_);
                for (int e = htid; e < B_ * (H_ / 4); e += 256) {
                    int b = e >> 6, k4 = e & 63;
                    *(float4*)(vrec + b * VST + k4 * 4) = hp[e];
                }
            }
            asm volatile("bar.sync 1, 256;" ::: "memory");
            // H2: recurrent GEMM (warps 6-11)
            if (h_on) {
                gemm64(wlo, whi, vrec + hkc * 64,
                       psum_h + (hrr * B_) * PSLOT + hkc);
            }
            asm volatile("bar.sync 1, 256;" ::: "memory");
            // H3: cell (warps 6-9) || warp 12 polls own-layer flags >= t+1
            if (htid < 128) {
                if (htid < jcB) {
                    while (ld_acq_cta(&sfl[0]) < t + 1) { }
                    const int jl = htid / B_;
                    const int b  = htid - jl * B_;
                    const float* px = psum_x +
                        (t & (XDEPTH - 1)) * ROWS_MAX * B_ * PSLOT;
                    float gs[4];
                    #pragma unroll
                    for (int gate = 0; gate < 4; gate++) {
                        const int r = gate * jc + jl;
                        const float* ph = psum_h + (r * B_ + b) * PSLOT;
                        const float* pxx = px + (r * B_ + b) * PSLOT;
                        float sh = (ph[0] + ph[1]) + (ph[2] + ph[3]);
                        float sx = (pxx[0] + pxx[1]) + (pxx[2] + pxx[3]);
                        gs[gate] = bsm[r] + sh + sx;
                    }
                    float ig = fmaf(0.5f, tanh_approx(0.5f * gs[0]), 0.5f);
                    float fg = fmaf(0.5f, tanh_approx(0.5f * gs[1]), 0.5f);
                    float gg = tanh_approx(gs[2]);
                    float og = fmaf(0.5f, tanh_approx(0.5f * gs[3]), 0.5f);
                    float c  = fmaf(fg, csm[htid], ig * gg);
                    csm[htid] = c;
                    float* hout = g_hseq +
                        ((size_t)(l * (T_ + 1) + t + 1)) * B_ * H_;
                    hout[(size_t)b * H_ + jbase + jl] = og * tanh_approx(c);
                }
                asm volatile("bar.sync 4, 128;" ::: "memory");
                if (htid == 0) st_rel_cta(&sfl[1], t + 1);
                if (htid == 1) {
                    asm volatile("st.release.gpu.global.b32 [%0], %1;"
                                 :: "l"(&g_prog[(l * NBLK + p) * 32]),
                                    "r"(t + 1));
                }
            } else if (wid == 12) {
                if ((tid & 31) < NBLK) {
                    const int* f = &g_prog[(l * NBLK + (tid & 31)) * 32];
                    while (ld_acq_gpu(f) < t + 1) { }
                }
            }
            asm volatile("bar.sync 1, 256;" ::: "memory");
        }
        // final cell states
        if (htid < jcB) {
            int jl = htid / B_, b = htid - jl * B_;
            out[((size_t)l * B_ + b) * H_ + jbase + jl] = csm[htid];
        }
    }
}

#define SMEM_FLOATS (XDEPTH * B_ * VST + B_ * VST \
                     + (XDEPTH + 1) * ROWS_MAX * B_ * PSLOT \
                     + JC_MAX * B_ + ROWS_MAX + 8)
#define SMEM_BYTES  (SMEM_FLOATS * (int)sizeof(float))

extern "C" void kernel_launch(void* const* d_in, const int* in_sizes, int n_in,
                              void* d_out, int out_size) {
    const float* x    = (const float*)d_in[0];
    const float* h0   = (const float*)d_in[1];
    const float* c0   = (const float*)d_in[2];
    const float* Wih0 = (const float*)d_in[3];
    const float* Wih  = (const float*)d_in[4];
    const float* Whh  = (const float*)d_in[5];
    const float* bih  = (const float*)d_in[6];
    const float* bhh  = (const float*)d_in[7];
    float* out = (float*)d_out;

    cudaFuncSetAttribute(lstm_pipeline_kernel,
                         cudaFuncAttributeMaxDynamicSharedMemorySize, SMEM_BYTES);

    lstm_init_kernel<<<64, 256>>>(h0);
    lstm_pipeline_kernel<<<L_ * NBLK, THREADS, SMEM_BYTES>>>(
        x, c0, Wih0, Wih, Whh, bih, bhh, out);
}